// round 1
// baseline (speedup 1.0000x reference)
#include <cuda_runtime.h>
#include <math.h>

#define S_TOK 8192
#define DIM   1024
#define FDIM  4096
#define NE    8
#define CAP   2560
#define NA    (S_TOK * 2)

// ---------------- static scratch (no allocations allowed) ----------------
__device__ float g_imp[NE];                         // sum of probs per expert
__device__ int   g_topk_e[NA];                      // expert id per assignment
__device__ float g_topk_g[NA];                      // gate value per assignment
__device__ int   g_pos[NA];                         // arrival position within expert
__device__ int   g_rowsrc[NE * CAP];                // slot -> source token
__device__ int   g_rows_used[NE];                   // min(count, CAP)
__device__ float g_h[(size_t)NE * CAP * FDIM];      // hidden activations (zero-init; pad rows never written)
__device__ float g_eout[(size_t)NE * CAP * DIM];    // expert outputs

// ---------------- tiny init ----------------
__global__ void k_zero() {
    if (threadIdx.x < NE) g_imp[threadIdx.x] = 0.f;
}

// ---------------- routing: warp per token ----------------
__global__ void k_route(const float* __restrict__ x, const float* __restrict__ wg) {
    __shared__ float sw[NE * DIM];
    __shared__ float simp[NE];
    int tid = threadIdx.x;

    const float4* wg4 = (const float4*)wg;
    float4* sw4 = (float4*)sw;
    for (int i = tid; i < NE * DIM / 4; i += 256) sw4[i] = wg4[i];
    if (tid < NE) simp[tid] = 0.f;
    __syncthreads();

    int warp = tid >> 5, lane = tid & 31;
    int t = blockIdx.x * 8 + warp;

    const float4* x4 = (const float4*)(x + (size_t)t * DIM);
    float acc[NE];
#pragma unroll
    for (int e = 0; e < NE; e++) acc[e] = 0.f;
#pragma unroll
    for (int i = 0; i < 8; i++) {
        float4 xv = x4[lane + i * 32];
#pragma unroll
        for (int e = 0; e < NE; e++) {
            float4 wv = ((const float4*)(sw + e * DIM))[lane + i * 32];
            acc[e] += xv.x * wv.x + xv.y * wv.y + xv.z * wv.z + xv.w * wv.w;
        }
    }
#pragma unroll
    for (int e = 0; e < NE; e++) {
#pragma unroll
        for (int off = 16; off > 0; off >>= 1)
            acc[e] += __shfl_xor_sync(0xffffffffu, acc[e], off);
    }

    if (lane == 0) {
        float m = acc[0];
#pragma unroll
        for (int e = 1; e < NE; e++) m = fmaxf(m, acc[e]);
        float p[NE];
        float s = 0.f;
#pragma unroll
        for (int e = 0; e < NE; e++) { p[e] = expf(acc[e] - m); s += p[e]; }
        float inv = 1.f / s;
#pragma unroll
        for (int e = 0; e < NE; e++) { p[e] *= inv; atomicAdd(&simp[e], p[e]); }

        // top-1 (lowest index on tie, strict >)
        int e0 = 0;
#pragma unroll
        for (int e = 1; e < NE; e++) if (p[e] > p[e0]) e0 = e;
        // top-2 among e != e0, lowest index on tie
        int e1 = (e0 == 0) ? 1 : 0;
#pragma unroll
        for (int e = 0; e < NE; e++) if (e != e0 && p[e] > p[e1]) e1 = e;

        g_topk_e[2 * t]     = e0;  g_topk_g[2 * t]     = p[e0];
        g_topk_e[2 * t + 1] = e1;  g_topk_g[2 * t + 1] = p[e1];
    }
    __syncthreads();
    if (tid < NE) atomicAdd(&g_imp[tid], simp[tid]);
}

// ---------------- exact arrival-order capacity scan (single block) ----------------
__global__ void k_scan(float* __restrict__ out, int out_size) {
    __shared__ int scnt[256][NE];
    __shared__ int stot[NE];
    int tid = threadIdx.x;

    int cnt[NE];
#pragma unroll
    for (int e = 0; e < NE; e++) cnt[e] = 0;
    int base = tid * 64;
    for (int j = 0; j < 64; j++) cnt[g_topk_e[base + j]]++;
#pragma unroll
    for (int e = 0; e < NE; e++) scnt[tid][e] = cnt[e];
    __syncthreads();

    if (tid < NE) {
        int run = 0;
        for (int i = 0; i < 256; i++) {
            int v = scnt[i][tid];
            scnt[i][tid] = run;
            run += v;
        }
        stot[tid] = run;
        g_rows_used[tid] = run < CAP ? run : CAP;
    }
    __syncthreads();

#pragma unroll
    for (int e = 0; e < NE; e++) cnt[e] = scnt[tid][e];
    for (int j = 0; j < 64; j++) {
        int a = base + j;
        int e = g_topk_e[a];
        int p = cnt[e]++;
        g_pos[a] = p;
        if (p < CAP) g_rowsrc[e * CAP + p] = a >> 1;
    }

    if (tid == 0) {
        float ssum = 0.f;
        for (int e = 0; e < NE; e++)
            ssum += (g_imp[e] / (float)S_TOK) * ((float)stot[e] / (float)S_TOK);
        if (out_size > S_TOK * DIM) out[S_TOK * DIM] = (float)NE * ssum;
    }
}

// ---------------- GEMM1: h = gelu(gather(x) @ W1^T + b1) ----------------
__global__ void __launch_bounds__(256, 2)
k_gemm1(const float* __restrict__ x, const float* __restrict__ W1,
        const float* __restrict__ b1) {
    int e = blockIdx.z;
    int nrows = g_rows_used[e];
    int row0 = blockIdx.y * 128;
    if (row0 >= nrows) return;
    int col0 = blockIdx.x * 128;

    __shared__ float As[16][128];
    __shared__ float Bs[16][128];

    int tid = threadIdx.x;
    int rA0 = tid >> 2,        sA0 = tid & 3;        // rows 0..63
    int rA1 = (tid + 256) >> 2, sA1 = tid & 3;       // rows 64..127

    int t0 = (row0 + rA0 < nrows) ? g_rowsrc[e * CAP + row0 + rA0] : 0;
    int t1 = (row0 + rA1 < nrows) ? g_rowsrc[e * CAP + row0 + rA1] : 0;
    const float* aptr0 = x + (size_t)t0 * DIM + sA0 * 4;
    const float* aptr1 = x + (size_t)t1 * DIM + sA1 * 4;

    const float* bbase = W1 + (size_t)e * FDIM * DIM;
    const float* bptr0 = bbase + (size_t)(col0 + rA0) * DIM + sA0 * 4;
    const float* bptr1 = bbase + (size_t)(col0 + rA1) * DIM + sA1 * 4;

    int ty = tid >> 4, tx = tid & 15;
    float acc[8][8];
#pragma unroll
    for (int i = 0; i < 8; i++)
#pragma unroll
        for (int j = 0; j < 8; j++) acc[i][j] = 0.f;

    for (int k0 = 0; k0 < DIM; k0 += 16) {
        float4 a0 = *(const float4*)(aptr0 + k0);
        float4 a1 = *(const float4*)(aptr1 + k0);
        float4 b0 = *(const float4*)(bptr0 + k0);
        float4 b1v = *(const float4*)(bptr1 + k0);
        __syncthreads();
        As[sA0 * 4 + 0][rA0] = a0.x; As[sA0 * 4 + 1][rA0] = a0.y;
        As[sA0 * 4 + 2][rA0] = a0.z; As[sA0 * 4 + 3][rA0] = a0.w;
        As[sA1 * 4 + 0][rA1] = a1.x; As[sA1 * 4 + 1][rA1] = a1.y;
        As[sA1 * 4 + 2][rA1] = a1.z; As[sA1 * 4 + 3][rA1] = a1.w;
        Bs[sA0 * 4 + 0][rA0] = b0.x; Bs[sA0 * 4 + 1][rA0] = b0.y;
        Bs[sA0 * 4 + 2][rA0] = b0.z; Bs[sA0 * 4 + 3][rA0] = b0.w;
        Bs[sA1 * 4 + 0][rA1] = b1v.x; Bs[sA1 * 4 + 1][rA1] = b1v.y;
        Bs[sA1 * 4 + 2][rA1] = b1v.z; Bs[sA1 * 4 + 3][rA1] = b1v.w;
        __syncthreads();
#pragma unroll
        for (int kk = 0; kk < 16; kk++) {
            float a[8], b[8];
#pragma unroll
            for (int i = 0; i < 8; i++) a[i] = As[kk][ty * 8 + i];
#pragma unroll
            for (int j = 0; j < 8; j++) b[j] = Bs[kk][tx * 8 + j];
#pragma unroll
            for (int i = 0; i < 8; i++)
#pragma unroll
                for (int j = 0; j < 8; j++) acc[i][j] += a[i] * b[j];
        }
    }

    const float* bb = b1 + (size_t)e * FDIM + col0;
#pragma unroll
    for (int i = 0; i < 8; i++) {
        int r = row0 + ty * 8 + i;
        if (r < nrows) {
            float* hrow = g_h + ((size_t)e * CAP + r) * FDIM + col0;
#pragma unroll
            for (int j = 0; j < 8; j++) {
                int c = tx * 8 + j;
                float v = acc[i][j] + bb[c];
                v = 0.5f * v * (1.f + erff(v * 0.70710678118654752f));
                hrow[c] = v;
            }
        }
    }
}

// ---------------- GEMM2: out = h @ W2^T + b2 + residual ----------------
__global__ void __launch_bounds__(256, 2)
k_gemm2(const float* __restrict__ x, const float* __restrict__ W2,
        const float* __restrict__ b2) {
    int e = blockIdx.z;
    int nrows = g_rows_used[e];
    int row0 = blockIdx.y * 128;
    if (row0 >= nrows) return;
    int col0 = blockIdx.x * 128;

    __shared__ float As[16][128];
    __shared__ float Bs[16][128];

    int tid = threadIdx.x;
    int rA0 = tid >> 2,         sA0 = tid & 3;
    int rA1 = (tid + 256) >> 2, sA1 = tid & 3;

    const float* abase = g_h + (size_t)e * CAP * FDIM;
    const float* aptr0 = abase + (size_t)(row0 + rA0) * FDIM + sA0 * 4;
    const float* aptr1 = abase + (size_t)(row0 + rA1) * FDIM + sA1 * 4;

    const float* bbase = W2 + (size_t)e * DIM * FDIM;
    const float* bptr0 = bbase + (size_t)(col0 + rA0) * FDIM + sA0 * 4;
    const float* bptr1 = bbase + (size_t)(col0 + rA1) * FDIM + sA1 * 4;

    int ty = tid >> 4, tx = tid & 15;
    float acc[8][8];
#pragma unroll
    for (int i = 0; i < 8; i++)
#pragma unroll
        for (int j = 0; j < 8; j++) acc[i][j] = 0.f;

    for (int k0 = 0; k0 < FDIM; k0 += 16) {
        float4 a0 = *(const float4*)(aptr0 + k0);
        float4 a1 = *(const float4*)(aptr1 + k0);
        float4 b0 = *(const float4*)(bptr0 + k0);
        float4 b1v = *(const float4*)(bptr1 + k0);
        __syncthreads();
        As[sA0 * 4 + 0][rA0] = a0.x; As[sA0 * 4 + 1][rA0] = a0.y;
        As[sA0 * 4 + 2][rA0] = a0.z; As[sA0 * 4 + 3][rA0] = a0.w;
        As[sA1 * 4 + 0][rA1] = a1.x; As[sA1 * 4 + 1][rA1] = a1.y;
        As[sA1 * 4 + 2][rA1] = a1.z; As[sA1 * 4 + 3][rA1] = a1.w;
        Bs[sA0 * 4 + 0][rA0] = b0.x; Bs[sA0 * 4 + 1][rA0] = b0.y;
        Bs[sA0 * 4 + 2][rA0] = b0.z; Bs[sA0 * 4 + 3][rA0] = b0.w;
        Bs[sA1 * 4 + 0][rA1] = b1v.x; Bs[sA1 * 4 + 1][rA1] = b1v.y;
        Bs[sA1 * 4 + 2][rA1] = b1v.z; Bs[sA1 * 4 + 3][rA1] = b1v.w;
        __syncthreads();
#pragma unroll
        for (int kk = 0; kk < 16; kk++) {
            float a[8], b[8];
#pragma unroll
            for (int i = 0; i < 8; i++) a[i] = As[kk][ty * 8 + i];
#pragma unroll
            for (int j = 0; j < 8; j++) b[j] = Bs[kk][tx * 8 + j];
#pragma unroll
            for (int i = 0; i < 8; i++)
#pragma unroll
                for (int j = 0; j < 8; j++) acc[i][j] += a[i] * b[j];
        }
    }

    const float* bb = b2 + (size_t)e * DIM + col0;
#pragma unroll
    for (int i = 0; i < 8; i++) {
        int r = row0 + ty * 8 + i;
        if (r < nrows) {
            int t = g_rowsrc[e * CAP + r];
            const float* xr = x + (size_t)t * DIM + col0;
            float* orow = g_eout + ((size_t)e * CAP + r) * DIM + col0;
#pragma unroll
            for (int j = 0; j < 8; j++) {
                int c = tx * 8 + j;
                orow[c] = acc[i][j] + bb[c] + xr[c];
            }
        }
    }
}

// ---------------- combine: y[t] = sum_k gate * expert_out ----------------
__global__ void k_combine(float* __restrict__ y) {
    int t = blockIdx.x;
    int tid = threadIdx.x;
    int a0 = 2 * t, a1 = a0 + 1;

    int e0 = g_topk_e[a0], p0 = g_pos[a0]; float gv0 = g_topk_g[a0];
    int e1 = g_topk_e[a1], p1 = g_pos[a1]; float gv1 = g_topk_g[a1];

    float4 r;
    r.x = 0.f; r.y = 0.f; r.z = 0.f; r.w = 0.f;

    if (p0 < CAP) {
        const float4* s = (const float4*)(g_eout + ((size_t)e0 * CAP + p0) * DIM);
        float4 v = s[tid];
        r.x += gv0 * v.x; r.y += gv0 * v.y; r.z += gv0 * v.z; r.w += gv0 * v.w;
    }
    if (p1 < CAP) {
        const float4* s = (const float4*)(g_eout + ((size_t)e1 * CAP + p1) * DIM);
        float4 v = s[tid];
        r.x += gv1 * v.x; r.y += gv1 * v.y; r.z += gv1 * v.z; r.w += gv1 * v.w;
    }
    ((float4*)(y + (size_t)t * DIM))[tid] = r;
}

// ---------------- launch ----------------
extern "C" void kernel_launch(void* const* d_in, const int* in_sizes, int n_in,
                              void* d_out, int out_size) {
    const float* x  = (const float*)d_in[0];
    const float* wg = (const float*)d_in[1];
    const float* W1 = (const float*)d_in[2];
    const float* b1 = (const float*)d_in[3];
    const float* W2 = (const float*)d_in[4];
    const float* b2 = (const float*)d_in[5];
    float* out = (float*)d_out;

    k_zero<<<1, 32>>>();
    k_route<<<S_TOK / 8, 256>>>(x, wg);
    k_scan<<<1, 256>>>(out, out_size);

    dim3 g1(FDIM / 128, (CAP + 127) / 128, NE);
    k_gemm1<<<g1, 256>>>(x, W1, b1);

    dim3 g2(DIM / 128, (CAP + 127) / 128, NE);
    k_gemm2<<<g2, 256>>>(x, W2, b2);

    k_combine<<<S_TOK, 256>>>(out);
}

// round 4
// speedup vs baseline: 2.4943x; 2.4943x over previous
#include <cuda_runtime.h>
#include <math.h>
#include <stdint.h>

#define S_TOK 8192
#define DIM   1024
#define FDIM  4096
#define NE    8
#define CAP   2560
#define NA    (S_TOK * 2)

// ---------------- static scratch ----------------
__device__ float g_imp[NE];
__device__ int   g_topk_e[NA];
__device__ float g_topk_g[NA];
__device__ int   g_pos[NA];
__device__ int   g_rowsrc[NE * CAP];
__device__ int   g_rows_used[NE];
__device__ float g_xbuf[(size_t)NE * CAP * DIM];   // dispatched tokens (pad rows zeroed)
__device__ float g_h[(size_t)NE * CAP * FDIM];     // hidden (pad rows stay 0)
__device__ float g_eout[(size_t)NE * CAP * DIM];   // expert outputs

// ---------------- helpers ----------------
__device__ __forceinline__ uint32_t smem_u32(const void* p) {
    uint32_t r;
    asm("{ .reg .u64 t; cvta.to.shared.u64 t, %1; cvt.u32.u64 %0, t; }" : "=r"(r) : "l"(p));
    return r;
}
__device__ __forceinline__ void cpa16(uint32_t s, const void* g) {
    asm volatile("cp.async.cg.shared.global [%0], [%1], 16;" :: "r"(s), "l"(g));
}
#define CP_COMMIT() asm volatile("cp.async.commit_group;")

__device__ __forceinline__ void ldsm4(uint32_t addr, uint32_t& r0, uint32_t& r1,
                                      uint32_t& r2, uint32_t& r3) {
    asm volatile("ldmatrix.sync.aligned.m8n8.x4.shared.b16 {%0,%1,%2,%3}, [%4];"
                 : "=r"(r0), "=r"(r1), "=r"(r2), "=r"(r3) : "r"(addr));
}
__device__ __forceinline__ uint32_t f2tf(uint32_t u) {
    uint32_t d;
    asm("cvt.rna.tf32.f32 %0, %1;" : "=r"(d) : "f"(__uint_as_float(u)));
    return d;
}
__device__ __forceinline__ void mma_tf32(float& c0, float& c1, float& c2, float& c3,
                                         uint32_t a0, uint32_t a1, uint32_t a2, uint32_t a3,
                                         uint32_t b0, uint32_t b1) {
    asm volatile("mma.sync.aligned.m16n8k8.row.col.f32.tf32.tf32.f32 "
                 "{%0,%1,%2,%3}, {%4,%5,%6,%7}, {%8,%9}, {%0,%1,%2,%3};"
                 : "+f"(c0), "+f"(c1), "+f"(c2), "+f"(c3)
                 : "r"(a0), "r"(a1), "r"(a2), "r"(a3), "r"(b0), "r"(b1));
}

// ---------------- tiny init ----------------
__global__ void k_zero() {
    if (threadIdx.x < NE) g_imp[threadIdx.x] = 0.f;
}

// ---------------- routing: warp per token ----------------
__global__ void k_route(const float* __restrict__ x, const float* __restrict__ wg) {
    __shared__ float sw[NE * DIM];
    __shared__ float simp[NE];
    int tid = threadIdx.x;

    const float4* wg4 = (const float4*)wg;
    float4* sw4 = (float4*)sw;
    for (int i = tid; i < NE * DIM / 4; i += 256) sw4[i] = wg4[i];
    if (tid < NE) simp[tid] = 0.f;
    __syncthreads();

    int warp = tid >> 5, lane = tid & 31;
    int t = blockIdx.x * 8 + warp;

    const float4* x4 = (const float4*)(x + (size_t)t * DIM);
    float acc[NE];
#pragma unroll
    for (int e = 0; e < NE; e++) acc[e] = 0.f;
#pragma unroll
    for (int i = 0; i < 8; i++) {
        float4 xv = x4[lane + i * 32];
#pragma unroll
        for (int e = 0; e < NE; e++) {
            float4 wv = ((const float4*)(sw + e * DIM))[lane + i * 32];
            acc[e] += xv.x * wv.x + xv.y * wv.y + xv.z * wv.z + xv.w * wv.w;
        }
    }
#pragma unroll
    for (int e = 0; e < NE; e++) {
#pragma unroll
        for (int off = 16; off > 0; off >>= 1)
            acc[e] += __shfl_xor_sync(0xffffffffu, acc[e], off);
    }

    if (lane == 0) {
        float m = acc[0];
#pragma unroll
        for (int e = 1; e < NE; e++) m = fmaxf(m, acc[e]);
        float p[NE];
        float s = 0.f;
#pragma unroll
        for (int e = 0; e < NE; e++) { p[e] = expf(acc[e] - m); s += p[e]; }
        float inv = 1.f / s;
#pragma unroll
        for (int e = 0; e < NE; e++) { p[e] *= inv; atomicAdd(&simp[e], p[e]); }

        int e0 = 0;
#pragma unroll
        for (int e = 1; e < NE; e++) if (p[e] > p[e0]) e0 = e;
        int e1 = (e0 == 0) ? 1 : 0;
#pragma unroll
        for (int e = 0; e < NE; e++) if (e != e0 && p[e] > p[e1]) e1 = e;

        g_topk_e[2 * t]     = e0;  g_topk_g[2 * t]     = p[e0];
        g_topk_e[2 * t + 1] = e1;  g_topk_g[2 * t + 1] = p[e1];
    }
    __syncthreads();
    if (tid < NE) atomicAdd(&g_imp[tid], simp[tid]);
}

// ---------------- exact arrival-order capacity scan ----------------
__global__ void k_scan(float* __restrict__ out, int out_size) {
    __shared__ int scnt[256][NE];
    __shared__ int stot[NE];
    int tid = threadIdx.x;

    int cnt[NE];
#pragma unroll
    for (int e = 0; e < NE; e++) cnt[e] = 0;
    int base = tid * 64;
    for (int j = 0; j < 64; j++) cnt[g_topk_e[base + j]]++;
#pragma unroll
    for (int e = 0; e < NE; e++) scnt[tid][e] = cnt[e];
    __syncthreads();

    if (tid < NE) {
        int run = 0;
        for (int i = 0; i < 256; i++) {
            int v = scnt[i][tid];
            scnt[i][tid] = run;
            run += v;
        }
        stot[tid] = run;
        g_rows_used[tid] = run < CAP ? run : CAP;
    }
    __syncthreads();

#pragma unroll
    for (int e = 0; e < NE; e++) cnt[e] = scnt[tid][e];
    for (int j = 0; j < 64; j++) {
        int a = base + j;
        int e = g_topk_e[a];
        int p = cnt[e]++;
        g_pos[a] = p;
        if (p < CAP) g_rowsrc[e * CAP + p] = a >> 1;
    }

    if (tid == 0) {
        float ssum = 0.f;
        for (int e = 0; e < NE; e++)
            ssum += (g_imp[e] / (float)S_TOK) * ((float)stot[e] / (float)S_TOK);
        if (out_size > S_TOK * DIM) out[S_TOK * DIM] = (float)NE * ssum;
    }
}

// ---------------- dispatch tokens into contiguous per-expert buffer ----------------
__global__ void k_dispatch(const float* __restrict__ x) {
    int p = blockIdx.x, e = blockIdx.y;
    int tid = threadIdx.x;  // 256
    float4* dst = (float4*)(g_xbuf + ((size_t)e * CAP + p) * DIM);
    if (p < g_rows_used[e]) {
        const float4* src = (const float4*)(x + (size_t)g_rowsrc[e * CAP + p] * DIM);
        dst[tid] = src[tid];
    } else {
        dst[tid] = make_float4(0.f, 0.f, 0.f, 0.f);
    }
}

// ---------------- mma.sync tf32 FFN GEMM ----------------
// CTA tile 128x128, K-chunks of 32. 8 warps: warp tile 64(M) x 32(N).
// smem stage: A[128][36] + B[128][36] floats = 36864 B, double buffered.
#define ROWPAD 36
#define STAGE_F (2 * 128 * ROWPAD)          // floats per stage (A+B)
#define SMEM_FFN (2 * STAGE_F * 4)          // bytes

template<int KTOT, int MODE>
__global__ void __launch_bounds__(256, 2)
k_ffn(const float* __restrict__ x, const float* __restrict__ W,
      const float* __restrict__ bias) {
    extern __shared__ float smf[];
    const uint32_t sb = smem_u32(smf);
    int e = blockIdx.z;
    int nrows = g_rows_used[e];
    int row0 = blockIdx.y * 128;
    if (row0 >= nrows) return;
    int col0 = blockIdx.x * 128;
    int tid = threadIdx.x, wid = tid >> 5, lane = tid & 31;
    int wm = wid & 1, wn = wid >> 1;           // warp grid 2(M) x 4(N)
    int gid = lane >> 2, tig = lane & 3;

    const float* Abase = (MODE ? g_h : g_xbuf) + ((size_t)e * CAP + row0) * KTOT;
    const float* Bbase = W + (size_t)e * (size_t)(MODE ? DIM : FDIM) * KTOT
                           + (size_t)col0 * KTOT;

    // cp.async mapping: thread -> (row = tid>>1, half = tid&1), 4x16B per matrix
    int ldrow = tid >> 1, ldhalf = tid & 1;
    const float* gA = Abase + (size_t)ldrow * KTOT + ldhalf * 16;
    const float* gB = Bbase + (size_t)ldrow * KTOT + ldhalf * 16;
    uint32_t sArow = ldrow * (ROWPAD * 4) + ldhalf * 64;         // byte offset in stage
    uint32_t sBrow = 128 * ROWPAD * 4 + sArow;

    // ldmatrix addresses (within stage, bytes)
    uint32_t aRow = wm * 64 + (lane & 15);
    uint32_t aCol16 = (lane >> 4) * 16;
    uint32_t aAddr = aRow * (ROWPAD * 4) + aCol16;               // + mt*16 rows + kk*32B
    uint32_t bRow = wn * 32 + ((lane >> 4) & 1) * 8 + (lane & 7);
    uint32_t bCol16 = ((lane >> 3) & 1) * 16;
    uint32_t bAddr = 128 * ROWPAD * 4 + bRow * (ROWPAD * 4) + bCol16;

    float acc[4][4][4];
#pragma unroll
    for (int i = 0; i < 4; i++)
#pragma unroll
        for (int j = 0; j < 4; j++)
#pragma unroll
            for (int q = 0; q < 4; q++) acc[i][j][q] = 0.f;

    const int NKC = KTOT / 32;
    const uint32_t stageB = STAGE_F * 4;

    // prologue: stage 0
    {
        uint32_t sa = sb + sArow, sbb = sb + sBrow;
#pragma unroll
        for (int g = 0; g < 4; g++) cpa16(sa + g * 16, gA + g * 4);
#pragma unroll
        for (int g = 0; g < 4; g++) cpa16(sbb + g * 16, gB + g * 4);
        CP_COMMIT();
    }

    for (int i = 0; i < NKC; i++) {
        int s = i & 1;
        if (i + 1 < NKC) {
            int so = 1 - s;
            const float* ga = gA + (i + 1) * 32;
            const float* gb = gB + (i + 1) * 32;
            uint32_t sa = sb + so * stageB + sArow;
            uint32_t sbb = sb + so * stageB + sBrow;
#pragma unroll
            for (int g = 0; g < 4; g++) cpa16(sa + g * 16, ga + g * 4);
#pragma unroll
            for (int g = 0; g < 4; g++) cpa16(sbb + g * 16, gb + g * 4);
            CP_COMMIT();
            asm volatile("cp.async.wait_group 1;");
        } else {
            asm volatile("cp.async.wait_group 0;");
        }
        __syncthreads();

        uint32_t base = sb + s * stageB;
#pragma unroll
        for (int kk = 0; kk < 4; kk++) {
            uint32_t aF[4][4], bF[4][2];
#pragma unroll
            for (int mt = 0; mt < 4; mt++) {
                ldsm4(base + aAddr + mt * 16 * (ROWPAD * 4) + kk * 32,
                      aF[mt][0], aF[mt][1], aF[mt][2], aF[mt][3]);
            }
            {   // nt pair 0/1
                uint32_t r0, r1, r2, r3;
                ldsm4(base + bAddr + kk * 32, r0, r1, r2, r3);
                bF[0][0] = r0; bF[0][1] = r1; bF[1][0] = r2; bF[1][1] = r3;
                ldsm4(base + bAddr + 16 * (ROWPAD * 4) + kk * 32, r0, r1, r2, r3);
                bF[2][0] = r0; bF[2][1] = r1; bF[3][0] = r2; bF[3][1] = r3;
            }
#pragma unroll
            for (int mt = 0; mt < 4; mt++)
#pragma unroll
                for (int q = 0; q < 4; q++) aF[mt][q] = f2tf(aF[mt][q]);
#pragma unroll
            for (int nt = 0; nt < 4; nt++) {
                bF[nt][0] = f2tf(bF[nt][0]);
                bF[nt][1] = f2tf(bF[nt][1]);
            }
#pragma unroll
            for (int mt = 0; mt < 4; mt++)
#pragma unroll
                for (int nt = 0; nt < 4; nt++)
                    mma_tf32(acc[mt][nt][0], acc[mt][nt][1], acc[mt][nt][2], acc[mt][nt][3],
                             aF[mt][0], aF[mt][1], aF[mt][2], aF[mt][3],
                             bF[nt][0], bF[nt][1]);
        }
        __syncthreads();
    }

    // ---------------- epilogue ----------------
    const float* bb = bias + (size_t)e * (MODE ? DIM : FDIM) + col0;
#pragma unroll
    for (int mt = 0; mt < 4; mt++) {
        int r0g = row0 + wm * 64 + mt * 16 + gid;
        int r1g = r0g + 8;
        bool ok0 = r0g < nrows, ok1 = r1g < nrows;
        const float* xr0 = nullptr;
        const float* xr1 = nullptr;
        float* d0;
        float* d1;
        if (MODE == 0) {
            d0 = g_h + ((size_t)e * CAP + r0g) * FDIM + col0;
            d1 = g_h + ((size_t)e * CAP + r1g) * FDIM + col0;
        } else {
            int t0 = ok0 ? g_rowsrc[e * CAP + r0g] : 0;
            int t1 = ok1 ? g_rowsrc[e * CAP + r1g] : 0;
            xr0 = x + (size_t)t0 * DIM + col0;
            xr1 = x + (size_t)t1 * DIM + col0;
            d0 = g_eout + ((size_t)e * CAP + r0g) * DIM + col0;
            d1 = g_eout + ((size_t)e * CAP + r1g) * DIM + col0;
        }
#pragma unroll
        for (int nt = 0; nt < 4; nt++) {
            int c = wn * 32 + nt * 8 + tig * 2;
            float bv0 = bb[c], bv1 = bb[c + 1];
            if (ok0) {
                float v0 = acc[mt][nt][0] + bv0;
                float v1 = acc[mt][nt][1] + bv1;
                if (MODE == 0) {
                    v0 = 0.5f * v0 * (1.f + erff(v0 * 0.70710678118654752f));
                    v1 = 0.5f * v1 * (1.f + erff(v1 * 0.70710678118654752f));
                } else {
                    v0 += xr0[c]; v1 += xr0[c + 1];
                }
                *(float2*)(d0 + c) = make_float2(v0, v1);
            }
            if (ok1) {
                float v0 = acc[mt][nt][2] + bv0;
                float v1 = acc[mt][nt][3] + bv1;
                if (MODE == 0) {
                    v0 = 0.5f * v0 * (1.f + erff(v0 * 0.70710678118654752f));
                    v1 = 0.5f * v1 * (1.f + erff(v1 * 0.70710678118654752f));
                } else {
                    v0 += xr1[c]; v1 += xr1[c + 1];
                }
                *(float2*)(d1 + c) = make_float2(v0, v1);
            }
        }
    }
}

// ---------------- combine ----------------
__global__ void k_combine(float* __restrict__ y) {
    int t = blockIdx.x;
    int tid = threadIdx.x;
    int a0 = 2 * t, a1 = a0 + 1;

    int e0 = g_topk_e[a0], p0 = g_pos[a0]; float gv0 = g_topk_g[a0];
    int e1 = g_topk_e[a1], p1 = g_pos[a1]; float gv1 = g_topk_g[a1];

    float4 r;
    r.x = 0.f; r.y = 0.f; r.z = 0.f; r.w = 0.f;

    if (p0 < CAP) {
        const float4* s = (const float4*)(g_eout + ((size_t)e0 * CAP + p0) * DIM);
        float4 v = s[tid];
        r.x += gv0 * v.x; r.y += gv0 * v.y; r.z += gv0 * v.z; r.w += gv0 * v.w;
    }
    if (p1 < CAP) {
        const float4* s = (const float4*)(g_eout + ((size_t)e1 * CAP + p1) * DIM);
        float4 v = s[tid];
        r.x += gv1 * v.x; r.y += gv1 * v.y; r.z += gv1 * v.z; r.w += gv1 * v.w;
    }
    ((float4*)(y + (size_t)t * DIM))[tid] = r;
}

// ---------------- launch ----------------
extern "C" void kernel_launch(void* const* d_in, const int* in_sizes, int n_in,
                              void* d_out, int out_size) {
    const float* x  = (const float*)d_in[0];
    const float* wg = (const float*)d_in[1];
    const float* W1 = (const float*)d_in[2];
    const float* b1 = (const float*)d_in[3];
    const float* W2 = (const float*)d_in[4];
    const float* b2 = (const float*)d_in[5];
    float* out = (float*)d_out;

    cudaFuncSetAttribute(k_ffn<1024, 0>, cudaFuncAttributeMaxDynamicSharedMemorySize, SMEM_FFN);
    cudaFuncSetAttribute(k_ffn<4096, 1>, cudaFuncAttributeMaxDynamicSharedMemorySize, SMEM_FFN);

    k_zero<<<1, 32>>>();
    k_route<<<S_TOK / 8, 256>>>(x, wg);
    k_scan<<<1, 256>>>(out, out_size);

    dim3 gd(CAP, NE);
    k_dispatch<<<gd, 256>>>(x);

    dim3 g1(FDIM / 128, CAP / 128, NE);   // (32, 20, 8)
    k_ffn<1024, 0><<<g1, 256, SMEM_FFN>>>(x, W1, b1);

    dim3 g2(DIM / 128, CAP / 128, NE);    // (8, 20, 8)
    k_ffn<4096, 1><<<g2, 256, SMEM_FFN>>>(x, W2, b2);

    k_combine<<<S_TOK, 256>>>(out);
}